// round 10
// baseline (speedup 1.0000x reference)
#include <cuda_runtime.h>
#include <math.h>

// out[b,c,:] = irfft( rfft(x,16384) * Kspec[c], 16384 )[:8192]
// Structure identical to R9 (two kernels, radix-8 Stockham, fused seams,
// 7 smem twiddle tables). Arithmetic core rewritten with packed f32x2 ops:
// complex values are 64-bit packed (lo=re, hi=im); add/sub = 1 instruction,
// conj = 1 XOR. 0.5 unpack factors folded into stored Kspec (Kc *= 0.5).

#define N_FFT   8192
#define HALF_N  4096
#define NT      1024
#define L_SEQ   8192
#define NCHAN   256
#define NROWS   2048

#define BUF_PAD 8704
#define SKEW(a) ((a) + ((a) >> 4))
#define TWT     1024

typedef unsigned long long c64;

__device__ c64 g_kspec[(size_t)NCHAN * (N_FFT + 1)];

__device__ __forceinline__ c64 PK2(float x, float y) {
    c64 r; asm("mov.b64 %0, {%1,%2};" : "=l"(r) : "f"(x), "f"(y)); return r;
}
__device__ __forceinline__ void UPK2(c64 a, float& x, float& y) {
    asm("mov.b64 {%0,%1}, %2;" : "=f"(x), "=f"(y) : "l"(a));
}
__device__ __forceinline__ c64 CADD(c64 a, c64 b) {
    c64 r; asm("add.rn.f32x2 %0, %1, %2;" : "=l"(r) : "l"(a), "l"(b)); return r;
}
// a - b  ==  fma(b, (-1,-1), a)   (exact)
__device__ __forceinline__ c64 CSUB(c64 a, c64 b, c64 n1) {
    c64 r; asm("fma.rn.f32x2 %0, %1, %2, %3;" : "=l"(r) : "l"(b), "l"(n1), "l"(a)); return r;
}
__device__ __forceinline__ c64 MULP(c64 a, c64 k) {
    c64 r; asm("mul.rn.f32x2 %0, %1, %2;" : "=l"(r) : "l"(a), "l"(k)); return r;
}
#define CONJ(a)  ((a) ^ 0x8000000000000000ull)
#define NEGLO(a) ((a) ^ 0x0000000080000000ull)

__device__ __forceinline__ c64 CMUL(c64 a, c64 b) {
    float ax, ay, bx, by; UPK2(a, ax, ay); UPK2(b, bx, by);
    return PK2(ax * bx - ay * by, ax * by + ay * bx);
}
__device__ __forceinline__ c64 CMULC(c64 a, c64 b) {   // a * conj(b)
    float ax, ay, bx, by; UPK2(a, ax, ay); UPK2(b, bx, by);
    return PK2(ax * bx + ay * by, ay * bx - ax * by);
}

#define N1C 0xBF800000BF800000ull     /* (-1.f,-1.f) */

template <int INV>
__device__ __forceinline__ void dft8p(c64* v) {
    const c64 n1 = N1C;
    const float u = 0.70710678118654752f;
    c64 apc = CADD(v[0], v[4]), amc = CSUB(v[0], v[4], n1);
    c64 bpd = CADD(v[2], v[6]), bmd = CSUB(v[2], v[6], n1);
    c64 E0 = CADD(apc, bpd), E2 = CSUB(apc, bpd, n1);
    float ax, ay, bx, by; UPK2(amc, ax, ay); UPK2(bmd, bx, by);
    c64 E1, E3;
    if (!INV) { E1 = PK2(ax + by, ay - bx); E3 = PK2(ax - by, ay + bx); }
    else      { E1 = PK2(ax - by, ay + bx); E3 = PK2(ax + by, ay - bx); }
    c64 apc2 = CADD(v[1], v[5]), amc2 = CSUB(v[1], v[5], n1);
    c64 bpd2 = CADD(v[3], v[7]), bmd2 = CSUB(v[3], v[7], n1);
    c64 O0 = CADD(apc2, bpd2), O2 = CSUB(apc2, bpd2, n1);
    float cx, cy, dx, dy; UPK2(amc2, cx, cy); UPK2(bmd2, dx, dy);
    float O1x, O1y, O3x, O3y;
    if (!INV) { O1x = cx + dy; O1y = cy - dx; O3x = cx - dy; O3y = cy + dx; }
    else      { O1x = cx - dy; O1y = cy + dx; O3x = cx + dy; O3y = cy - dx; }
    float o2x, o2y; UPK2(O2, o2x, o2y);
    c64 T1, T2, T3;
    if (!INV) {
        T1 = PK2(u * (O1x + O1y), u * (O1y - O1x));
        T2 = PK2(o2y, -o2x);
        T3 = PK2(u * (O3y - O3x), -u * (O3x + O3y));
    } else {
        T1 = PK2(u * (O1x - O1y), u * (O1x + O1y));
        T2 = PK2(-o2y, o2x);
        T3 = PK2(-u * (O3x + O3y), u * (O3x - O3y));
    }
    v[0] = CADD(E0, O0); v[4] = CSUB(E0, O0, n1);
    v[1] = CADD(E1, T1); v[5] = CSUB(E1, T1, n1);
    v[2] = CADD(E2, T2); v[6] = CSUB(E2, T2, n1);
    v[3] = CADD(E3, T3); v[7] = CSUB(E3, T3, n1);
}

// forward dft8 with v[4..7] == 0 implied
__device__ __forceinline__ void dft8_halfp(c64* v) {
    const c64 n1 = N1C;
    const float u = 0.70710678118654752f;
    c64 E0 = CADD(v[0], v[2]), E2 = CSUB(v[0], v[2], n1);
    float ax, ay, bx, by; UPK2(v[0], ax, ay); UPK2(v[2], bx, by);
    c64 E1 = PK2(ax + by, ay - bx), E3 = PK2(ax - by, ay + bx);
    c64 O0 = CADD(v[1], v[3]), O2 = CSUB(v[1], v[3], n1);
    float cx, cy, dx, dy; UPK2(v[1], cx, cy); UPK2(v[3], dx, dy);
    float O1x = cx + dy, O1y = cy - dx, O3x = cx - dy, O3y = cy + dx;
    float o2x, o2y; UPK2(O2, o2x, o2y);
    c64 T1 = PK2(u * (O1x + O1y), u * (O1y - O1x));
    c64 T2 = PK2(o2y, -o2x);
    c64 T3 = PK2(u * (O3y - O3x), -u * (O3x + O3y));
    v[0] = CADD(E0, O0); v[4] = CSUB(E0, O0, n1);
    v[1] = CADD(E1, T1); v[5] = CSUB(E1, T1, n1);
    v[2] = CADD(E2, T2); v[6] = CSUB(E2, T2, n1);
    v[3] = CADD(E3, T3); v[7] = CSUB(E3, T3, n1);
}

// radix-8 Stockham stage, 7 twiddle tables tws[(m-1)*1024 + e] = W^{m e}
template <int INV>
__device__ __forceinline__ void stage_r8(const c64* __restrict__ x, c64* __restrict__ y,
                                         const c64* __restrict__ tws, int s, int tid) {
    const int q = tid & (s - 1);
    const int e = tid - q;
    c64 v[8];
#pragma unroll
    for (int j = 0; j < 8; j++) v[j] = x[SKEW(tid + (j << 10))];
    dft8p<INV>(v);
    const int o = q + (e << 3);
    y[SKEW(o)] = v[0];
#pragma unroll
    for (int m = 1; m < 8; m++) {
        c64 w = tws[((m - 1) << 10) + e];
        y[SKEW(o + m * s)] = INV ? CMULC(v[m], w) : CMUL(w, v[m]);
    }
}

__device__ __forceinline__ void stage1_write(c64* __restrict__ y, const c64* v,
                                             const c64* __restrict__ tws, int tid) {
    const int o = tid << 3;
    y[SKEW(o)] = v[0];
#pragma unroll
    for (int m = 1; m < 8; m++)
        y[SKEW(o + m)] = CMUL(tws[((m - 1) << 10) + tid], v[m]);
}

__device__ __forceinline__ void fill_tw(c64* tws, c64* twh, int tid) {
    float s, c;
#pragma unroll
    for (int m = 1; m <= 7; m++) {
        sincospif((float)(m * tid) * (1.0f / 4096.0f), &s, &c);
        tws[((m - 1) << 10) + tid] = PK2(c, -s);
    }
#pragma unroll
    for (int k = tid; k <= 2048; k += NT) {
        sincospif((float)k * (1.0f / 8192.0f), &s, &c);
        twh[k] = PK2(c, -s);
    }
}

// unpack WITHOUT 0.5 (returns doubled X): X2k, X2n from Z[k], Z[8192-k]
__device__ __forceinline__ void unpack2(c64 Zk, c64 Zn, c64 E, c64* Xk, c64* Xn) {
    const c64 n1 = N1C;
    c64 A = CADD(Zk, CONJ(Zn));                 // 2A
    c64 D = CSUB(Zk, CONJ(Zn), n1);             // 2D
    float dx, dy; UPK2(D, dx, dy);
    c64 B = PK2(dy, -dx);                       // 2B
    c64 EB = CMUL(E, B);
    *Xk = CADD(A, EB);
    *Xn = CONJ(CSUB(A, EB, n1));
}

// spectral pair with Kstored = K/(2N): consumes doubled X -> W scaled 1/N
__device__ __forceinline__ void spec_pair(c64 Zk, c64 Zn, c64 Kk, c64 Kn, c64 E,
                                          c64* Wk, c64* Wn) {
    const c64 n1 = N1C;
    const c64 hf = 0x3F0000003F000000ull;       // (0.5f, 0.5f)
    c64 Xk, Xn;
    unpack2(Zk, Zn, E, &Xk, &Xn);
    c64 Yk = CMUL(Xk, Kk);
    c64 Yn = CMUL(Xn, Kn);
    c64 Ay = MULP(CADD(Yk, CONJ(Yn)), hf);
    c64 Dy = MULP(CSUB(Yk, CONJ(Yn), n1), hf);
    c64 By = CMULC(Dy, E);
    float axx, ayy, bxx, byy; UPK2(Ay, axx, ayy); UPK2(By, bxx, byy);
    *Wk = PK2(axx - byy, ayy + bxx);
    *Wn = PK2(axx + byy, -ayy + bxx);
}

__device__ __forceinline__ float smooth_squash(const float* rk, int i) {
    float ssum = 0.f;
#pragma unroll
    for (int d = -3; d <= 3; d++) {
        int j = i + d;
        j = (j < 0) ? -j : j;
        j = (j > L_SEQ - 1) ? (2 * (L_SEQ - 1) - j) : j;
        ssum += rk[j];
    }
    float v = ssum * (1.0f / 7.0f);
    float a = fabsf(v) - 0.003f;
    return (a > 0.f) ? copysignf(a, v) : 0.f;
}

// smem: b0[BUF_PAD] | b1[BUF_PAD] | tws[7*1024] | twh[2052]
#define SMEM_BYTES ((2 * BUF_PAD + 7 * TWT + 2052) * (int)sizeof(c64))

// ---------------------------------------------------------------------------
__global__ void __launch_bounds__(NT, 1) kspec_kernel(const float* __restrict__ kern) {
    extern __shared__ c64 sm2[];
    c64* b0  = sm2;
    c64* b1  = sm2 + BUF_PAD;
    c64* tws = sm2 + 2 * BUF_PAD;
    c64* twh = tws + 7 * TWT;
    float* rk = (float*)b1;

    const int c   = blockIdx.x;
    const int tid = threadIdx.x;
    const float* kr = kern + (size_t)c * L_SEQ;

    for (int i = tid; i < L_SEQ; i += NT) rk[i] = kr[i];
    fill_tw(tws, twh, tid);
    __syncthreads();

    {   // fused stage 1 from smooth/squash registers
        c64 v[8];
#pragma unroll
        for (int j = 0; j < 4; j++) {
            const int n = tid + (j << 10);
            v[j] = PK2(smooth_squash(rk, 2 * n), smooth_squash(rk, 2 * n + 1));
        }
        dft8_halfp(v);
        stage1_write(b0, v, tws, tid);
    }
    __syncthreads();
    stage_r8<0>(b0, b1, tws, 8, tid);   __syncthreads();
    stage_r8<0>(b1, b0, tws, 64, tid);  __syncthreads();
    stage_r8<0>(b0, b1, tws, 512, tid); __syncthreads();
    // P = b1; fused r2 finisher + unpack + store. Stored scale = 1/(2N).
    c64* Kc = g_kspec + (size_t)c * (N_FFT + 1);
    const c64 n1 = N1C;
    const float s2 = 0.5f / (float)N_FFT;           // for true-valued entries
    const float s4 = 0.25f / (float)N_FFT;          // for doubled X entries
    const c64 s4p = PK2(s4, s4);
#pragma unroll 1
    for (int u = 0; u < 2; u++) {
        const int q = tid + (u << 10);
        if (q == 0) {
            c64 Pa = b1[SKEW(0)],    Pb = b1[SKEW(4096)];
            c64 Pc = b1[SKEW(2048)], Pd = b1[SKEW(6144)];
            c64 Z0 = CADD(Pa, Pb), Z4 = CSUB(Pa, Pb, n1);
            c64 Z2 = CADD(Pc, Pd), Z6 = CSUB(Pc, Pd, n1);
            float z0x, z0y; UPK2(Z0, z0x, z0y);
            Kc[0]     = PK2((z0x + z0y) * s2, 0.f);
            Kc[N_FFT] = PK2((z0x - z0y) * s2, 0.f);
            float z4x, z4y; UPK2(Z4, z4x, z4y);
            Kc[4096]  = PK2(z4x * s2, -z4y * s2);
            c64 X2, X6;
            unpack2(Z2, Z6, twh[2048], &X2, &X6);
            Kc[2048] = MULP(X2, s4p);
            Kc[6144] = MULP(X6, s4p);
        } else {
            const int r = 4096 - q;
            c64 Pa = b1[SKEW(q)], Pb = b1[SKEW(q + 4096)];
            c64 Pc = b1[SKEW(r)], Pd = b1[SKEW(r + 4096)];
            c64 Zq = CADD(Pa, Pb), Zq4 = CSUB(Pa, Pb, n1);
            c64 Zr = CADD(Pc, Pd), Znq = CSUB(Pc, Pd, n1);
            c64 Eq = twh[q];
            float eqx, eqy; UPK2(Eq, eqx, eqy);
            c64 Er = PK2(-eqy, -eqx);               // E(4096-q)
            c64 Xq, Xnq, Xr, Xpq;
            unpack2(Zq, Znq, Eq, &Xq, &Xnq);
            unpack2(Zr, Zq4, Er, &Xr, &Xpq);
            Kc[q]         = MULP(Xq, s4p);
            Kc[N_FFT - q] = MULP(Xnq, s4p);
            Kc[r]         = MULP(Xr, s4p);
            Kc[4096 + q]  = MULP(Xpq, s4p);
        }
    }
}

// ---------------------------------------------------------------------------
__global__ void __launch_bounds__(NT, 1) conv_kernel(const float* __restrict__ x,
                                                     float* __restrict__ out) {
    extern __shared__ c64 sm2[];
    c64* b0  = sm2;
    c64* b1  = sm2 + BUF_PAD;
    c64* tws = sm2 + 2 * BUF_PAD;
    c64* twh = tws + 7 * TWT;

    const int row = blockIdx.x;
    const int c   = row & (NCHAN - 1);
    const int tid = threadIdx.x;
    const c64* xr = (const c64*)(x + (size_t)row * L_SEQ);

    fill_tw(tws, twh, tid);
    __syncthreads();

    {   // fwd stage 1: global read fused (upper half zero)
        c64 v[8];
#pragma unroll
        for (int j = 0; j < 4; j++) v[j] = xr[tid + (j << 10)];
        dft8_halfp(v);
        stage1_write(b0, v, tws, tid);
    }
    __syncthreads();
    stage_r8<0>(b0, b1, tws, 8, tid);   __syncthreads();
    stage_r8<0>(b1, b0, tws, 64, tid);  __syncthreads();
    stage_r8<0>(b0, b1, tws, 512, tid); __syncthreads();
    // P = b1

    // fused: fwd r2 finisher + spectral multiply + inv r2 opener -> b0
    const c64* Kc = g_kspec + (size_t)c * (N_FFT + 1);
    const c64 n1 = N1C;
#pragma unroll 1
    for (int u = 0; u < 2; u++) {
        const int q = tid + (u << 10);
        if (q == 0) {
            c64 Pa = b1[SKEW(0)],    Pb = b1[SKEW(4096)];
            c64 Pc = b1[SKEW(2048)], Pd = b1[SKEW(6144)];
            c64 Z0 = CADD(Pa, Pb), Z4 = CSUB(Pa, Pb, n1);
            c64 Z2 = CADD(Pc, Pd), Z6 = CSUB(Pc, Pd, n1);
            float z0x, z0y; UPK2(Z0, z0x, z0y);
            float X0 = z0x + z0y, XN = z0x - z0y;
            float k0x, k0y, knx, kny;
            UPK2(Kc[0], k0x, k0y); UPK2(Kc[N_FFT], knx, kny);
            float y0x = X0 * k0x, y0y = X0 * k0y;
            float ynx = XN * knx, yny = XN * kny;
            // Kstored = K/(2N): drop the 0.5 here to compensate
            float Ayx = y0x + ynx, Ayy = y0y - yny;
            float Dyx = y0x - ynx, Dyy = y0y + yny;
            c64 W0 = PK2(Ayx - Dyy, Ayy + Dyx);
            c64 W4, Wd;
            spec_pair(Z4, Z4, Kc[4096], Kc[4096], PK2(0.f, -1.f), &W4, &Wd);
            c64 W2, W6;
            spec_pair(Z2, Z6, Kc[2048], Kc[6144], twh[2048], &W2, &W6);
            b0[SKEW(0)] = CADD(W0, W4);
            b0[SKEW(1)] = CSUB(W0, W4, n1);
            b0[SKEW(4096)] = CADD(W2, W6);
            c64 t = CSUB(W2, W6, n1);               // * i
            float tx, ty; UPK2(t, tx, ty);
            b0[SKEW(4097)] = PK2(-ty, tx);
        } else {
            const int r = 4096 - q;
            c64 Pa = b1[SKEW(q)], Pb = b1[SKEW(q + 4096)];
            c64 Pc = b1[SKEW(r)], Pd = b1[SKEW(r + 4096)];
            c64 Zq = CADD(Pa, Pb), Zq4 = CSUB(Pa, Pb, n1);
            c64 Zr = CADD(Pc, Pd), Znq = CSUB(Pc, Pd, n1);
            c64 Eq = twh[q];
            float eqx, eqy; UPK2(Eq, eqx, eqy);
            c64 Er = PK2(-eqy, -eqx);
            c64 Wq, Wnq, Wr, Wpq;
            spec_pair(Zq, Znq, Kc[q], Kc[N_FFT - q], Eq, &Wq, &Wnq);
            spec_pair(Zr, Zq4, Kc[r], Kc[4096 + q], Er, &Wr, &Wpq);
            c64 wq = CMUL(Eq, Eq);                  // W^q
            c64 wr = NEGLO(wq);                     // Er^2 = (-wq.x, wq.y)... see below
            // Er^2 = -conj(Eq^2): (-wq.x, wq.y) -> NEGLO flips lo sign ✓
            b0[SKEW(2 * q)]     = CADD(Wq, Wpq);
            b0[SKEW(2 * q + 1)] = CMULC(CSUB(Wq, Wpq, n1), wq);
            b0[SKEW(2 * r)]     = CADD(Wr, Wnq);
            b0[SKEW(2 * r + 1)] = CMULC(CSUB(Wr, Wnq, n1), wr);
        }
    }
    __syncthreads();

    stage_r8<1>(b0, b1, tws, 2, tid);   __syncthreads();
    stage_r8<1>(b1, b0, tws, 16, tid);  __syncthreads();
    stage_r8<1>(b0, b1, tws, 128, tid); __syncthreads();

    {   // final inverse stage s=1024 (twiddle-free): store first half to global
        c64 v[8];
#pragma unroll
        for (int j = 0; j < 8; j++) v[j] = b1[SKEW(tid + (j << 10))];
        dft8p<1>(v);
        c64* outr = (c64*)(out + (size_t)row * L_SEQ);
#pragma unroll
        for (int j = 0; j < 4; j++) outr[tid + (j << 10)] = v[j];
    }
}

// ---------------------------------------------------------------------------
extern "C" void kernel_launch(void* const* d_in, const int* in_sizes, int n_in,
                              void* d_out, int out_size) {
    const float* x;
    const float* kern;
    if (in_sizes[0] == NROWS * L_SEQ) {
        x    = (const float*)d_in[0];
        kern = (const float*)d_in[1];
    } else {
        x    = (const float*)d_in[1];
        kern = (const float*)d_in[0];
    }
    float* out = (float*)d_out;

    cudaFuncSetAttribute(kspec_kernel, cudaFuncAttributeMaxDynamicSharedMemorySize, SMEM_BYTES);
    cudaFuncSetAttribute(conv_kernel,  cudaFuncAttributeMaxDynamicSharedMemorySize, SMEM_BYTES);

    kspec_kernel<<<NCHAN, NT, SMEM_BYTES>>>(kern);
    conv_kernel<<<NROWS, NT, SMEM_BYTES>>>(x, out);
}

// round 11
// speedup vs baseline: 1.0428x; 1.0428x over previous
#include <cuda_runtime.h>
#include <math.h>

// out[b,c,:] = irfft( rfft(x,16384) * Kspec[c], 16384 )[:8192]
// R9 float2 base (radix-8 Stockham, fused seams, 7 smem twiddle tables)
// + per-pass skew: writes of s=8 / s=2 stages use skew a+2(a>>4) (conflict-free
// for their scatter pattern); all other passes use a+(a>>4). Reads use the
// producer pass's skew (stride-1 reads are conflict-free under both).

#define N_FFT   8192
#define HALF_N  4096
#define NT      1024
#define L_SEQ   8192
#define NCHAN   256
#define NROWS   2048

#define BUF_PAD 9216
#define SKM(a,M) ((a) + (M) * ((a) >> 4))
#define TWT     1024

__device__ float2 g_kspec[(size_t)NCHAN * (N_FFT + 1)];

__device__ __forceinline__ float2 cmul(float2 a, float2 b) {
    return make_float2(a.x * b.x - a.y * b.y, a.x * b.y + a.y * b.x);
}
__device__ __forceinline__ float2 cmulc(float2 a, float2 b) {   // a * conj(b)
    return make_float2(a.x * b.x + a.y * b.y, a.y * b.x - a.x * b.y);
}
__device__ __forceinline__ float2 cadd(float2 a, float2 b) { return make_float2(a.x + b.x, a.y + b.y); }
__device__ __forceinline__ float2 csub(float2 a, float2 b) { return make_float2(a.x - b.x, a.y - b.y); }

template <int INV>
__device__ __forceinline__ void dft8(float2* v) {
    const float u = 0.70710678118654752f;
    float2 apc = cadd(v[0], v[4]), amc = csub(v[0], v[4]);
    float2 bpd = cadd(v[2], v[6]), bmd = csub(v[2], v[6]);
    float2 E0 = cadd(apc, bpd), E2 = csub(apc, bpd), E1, E3;
    if (!INV) { E1 = make_float2(amc.x + bmd.y, amc.y - bmd.x); E3 = make_float2(amc.x - bmd.y, amc.y + bmd.x); }
    else      { E1 = make_float2(amc.x - bmd.y, amc.y + bmd.x); E3 = make_float2(amc.x + bmd.y, amc.y - bmd.x); }
    apc = cadd(v[1], v[5]); amc = csub(v[1], v[5]);
    bpd = cadd(v[3], v[7]); bmd = csub(v[3], v[7]);
    float2 O0 = cadd(apc, bpd), O2 = csub(apc, bpd), O1, O3;
    if (!INV) { O1 = make_float2(amc.x + bmd.y, amc.y - bmd.x); O3 = make_float2(amc.x - bmd.y, amc.y + bmd.x); }
    else      { O1 = make_float2(amc.x - bmd.y, amc.y + bmd.x); O3 = make_float2(amc.x + bmd.y, amc.y - bmd.x); }
    float2 T1, T2, T3;
    if (!INV) {
        T1 = make_float2(u * (O1.x + O1.y), u * (O1.y - O1.x));
        T2 = make_float2(O2.y, -O2.x);
        T3 = make_float2(u * (O3.y - O3.x), -u * (O3.x + O3.y));
    } else {
        T1 = make_float2(u * (O1.x - O1.y), u * (O1.x + O1.y));
        T2 = make_float2(-O2.y, O2.x);
        T3 = make_float2(-u * (O3.x + O3.y), u * (O3.x - O3.y));
    }
    v[0] = cadd(E0, O0); v[4] = csub(E0, O0);
    v[1] = cadd(E1, T1); v[5] = csub(E1, T1);
    v[2] = cadd(E2, T2); v[6] = csub(E2, T2);
    v[3] = cadd(E3, T3); v[7] = csub(E3, T3);
}

// forward dft8 with v[4..7] == 0 implied
__device__ __forceinline__ void dft8_half(float2* v) {
    const float u = 0.70710678118654752f;
    float2 E0 = cadd(v[0], v[2]), E2 = csub(v[0], v[2]);
    float2 E1 = make_float2(v[0].x + v[2].y, v[0].y - v[2].x);
    float2 E3 = make_float2(v[0].x - v[2].y, v[0].y + v[2].x);
    float2 O0 = cadd(v[1], v[3]), O2 = csub(v[1], v[3]);
    float2 O1 = make_float2(v[1].x + v[3].y, v[1].y - v[3].x);
    float2 O3 = make_float2(v[1].x - v[3].y, v[1].y + v[3].x);
    float2 T1 = make_float2(u * (O1.x + O1.y), u * (O1.y - O1.x));
    float2 T2 = make_float2(O2.y, -O2.x);
    float2 T3 = make_float2(u * (O3.y - O3.x), -u * (O3.x + O3.y));
    v[0] = cadd(E0, O0); v[4] = csub(E0, O0);
    v[1] = cadd(E1, T1); v[5] = csub(E1, T1);
    v[2] = cadd(E2, T2); v[6] = csub(E2, T2);
    v[3] = cadd(E3, T3); v[7] = csub(E3, T3);
}

// radix-8 Stockham stage; RM/WM = skew multipliers for read/write buffers
template <int INV, int RM, int WM>
__device__ __forceinline__ void stage_r8(const float2* __restrict__ x, float2* __restrict__ y,
                                         const float2* __restrict__ tws, int s, int tid) {
    const int q = tid & (s - 1);
    const int e = tid - q;
    float2 v[8];
#pragma unroll
    for (int j = 0; j < 8; j++) v[j] = x[SKM(tid + (j << 10), RM)];
    dft8<INV>(v);
    const int o = q + (e << 3);
    y[SKM(o, WM)] = v[0];
#pragma unroll
    for (int m = 1; m < 8; m++) {
        float2 w = tws[((m - 1) << 10) + e];
        y[SKM(o + m * s, WM)] = INV ? cmulc(v[m], w) : cmul(w, v[m]);
    }
}

// stage-1 (s=1) write from registers, e = tid  (skew mult 1: conflict-free)
__device__ __forceinline__ void stage1_write(float2* __restrict__ y, const float2* v,
                                             const float2* __restrict__ tws, int tid) {
    const int o = tid << 3;
    y[SKM(o, 1)] = v[0];
#pragma unroll
    for (int m = 1; m < 8; m++) {
        float2 w = tws[((m - 1) << 10) + tid];
        y[SKM(o + m, 1)] = cmul(w, v[m]);
    }
}

// fill tables: tws[(m-1)*1024+j] = e^{-2 pi i m j/8192}; twh[k]=e^{-i pi k/8192}
__device__ __forceinline__ void fill_tw(float2* tws, float2* twh, int tid) {
    float s, c;
#pragma unroll
    for (int m = 1; m <= 7; m++) {
        sincospif((float)(m * tid) * (1.0f / 4096.0f), &s, &c);
        tws[((m - 1) << 10) + tid] = make_float2(c, -s);
    }
#pragma unroll
    for (int k = tid; k <= 2048; k += NT) {
        sincospif((float)k * (1.0f / 8192.0f), &s, &c);
        twh[k] = make_float2(c, -s);
    }
}

// unpack pair: Z[k], Z[8192-k], E=e^{-i pi k/8192} -> X[k], X[8192-k]
__device__ __forceinline__ void unpack_pair(float2 Zk, float2 Zn, float2 E,
                                            float2* Xk, float2* Xn) {
    float2 A = make_float2(0.5f * (Zk.x + Zn.x), 0.5f * (Zk.y - Zn.y));
    float2 D = make_float2(0.5f * (Zk.x - Zn.x), 0.5f * (Zk.y + Zn.y));
    float2 B = make_float2(D.y, -D.x);
    float2 EB = cmul(E, B);
    *Xk = make_float2(A.x + EB.x, A.y + EB.y);
    *Xn = make_float2(A.x - EB.x, -(A.y - EB.y));
}

__device__ __forceinline__ void spec_pair(float2 Zk, float2 Zn, float2 Kk, float2 Kn,
                                          float2 E, float2* Wk, float2* Wn) {
    float2 Xk, Xn;
    unpack_pair(Zk, Zn, E, &Xk, &Xn);
    float2 Yk = cmul(Xk, Kk);
    float2 Yn = cmul(Xn, Kn);
    float2 Ay = make_float2(0.5f * (Yk.x + Yn.x), 0.5f * (Yk.y - Yn.y));
    float2 Dy = make_float2(0.5f * (Yk.x - Yn.x), 0.5f * (Yk.y + Yn.y));
    float2 By = cmulc(Dy, E);
    *Wk = make_float2(Ay.x - By.y,  Ay.y + By.x);
    *Wn = make_float2(Ay.x + By.y, -Ay.y + By.x);
}

__device__ __forceinline__ float smooth_squash(const float* rk, int i) {
    float ssum = 0.f;
#pragma unroll
    for (int d = -3; d <= 3; d++) {
        int j = i + d;
        j = (j < 0) ? -j : j;
        j = (j > L_SEQ - 1) ? (2 * (L_SEQ - 1) - j) : j;
        ssum += rk[j];
    }
    float v = ssum * (1.0f / 7.0f);
    float a = fabsf(v) - 0.003f;
    return (a > 0.f) ? copysignf(a, v) : 0.f;
}

// smem: b0[BUF_PAD] | b1[BUF_PAD] | tws[7*1024] | twh[2052]
#define SMEM_BYTES ((2 * BUF_PAD + 7 * TWT + 2052) * (int)sizeof(float2))

// ---------------------------------------------------------------------------
__global__ void __launch_bounds__(NT, 1) kspec_kernel(const float* __restrict__ kern) {
    extern __shared__ float2 sm2[];
    float2* b0  = sm2;
    float2* b1  = sm2 + BUF_PAD;
    float2* tws = sm2 + 2 * BUF_PAD;
    float2* twh = tws + 7 * TWT;
    float*  rk  = (float*)b1;

    const int c   = blockIdx.x;
    const int tid = threadIdx.x;
    const float* kr = kern + (size_t)c * L_SEQ;

    for (int i = tid; i < L_SEQ; i += NT) rk[i] = kr[i];
    fill_tw(tws, twh, tid);
    __syncthreads();

    {   // fused stage 1 from smooth/squash registers -> b0 (skew 1)
        float2 v[8];
#pragma unroll
        for (int j = 0; j < 4; j++) {
            const int n = tid + (j << 10);
            v[j] = make_float2(smooth_squash(rk, 2 * n), smooth_squash(rk, 2 * n + 1));
        }
        dft8_half(v);
        stage1_write(b0, v, tws, tid);
    }
    __syncthreads();
    stage_r8<0,1,2>(b0, b1, tws, 8, tid);   __syncthreads();  // W conflict-free under SK2
    stage_r8<0,2,1>(b1, b0, tws, 64, tid);  __syncthreads();
    stage_r8<0,1,1>(b0, b1, tws, 512, tid); __syncthreads();
    // P = b1 (skew 1); fused r2 finisher + unpack + store (scaled 1/N)
    float2* Kc = g_kspec + (size_t)c * (N_FFT + 1);
    const float inv = 1.0f / (float)N_FFT;
#pragma unroll 1
    for (int u = 0; u < 2; u++) {
        const int q = tid + (u << 10);
        if (q == 0) {
            float2 Pa = b1[SKM(0,1)],    Pb = b1[SKM(4096,1)];
            float2 Pc = b1[SKM(2048,1)], Pd = b1[SKM(6144,1)];
            float2 Z0 = cadd(Pa, Pb), Z4 = csub(Pa, Pb);
            float2 Z2 = cadd(Pc, Pd), Z6 = csub(Pc, Pd);
            Kc[0]     = make_float2((Z0.x + Z0.y) * inv, 0.f);
            Kc[N_FFT] = make_float2((Z0.x - Z0.y) * inv, 0.f);
            Kc[4096]  = make_float2(Z4.x * inv, -Z4.y * inv);
            float2 X2, X6;
            unpack_pair(Z2, Z6, twh[2048], &X2, &X6);
            Kc[2048] = make_float2(X2.x * inv, X2.y * inv);
            Kc[6144] = make_float2(X6.x * inv, X6.y * inv);
        } else {
            const int r = 4096 - q;
            float2 Pa = b1[SKM(q,1)], Pb = b1[SKM(q + 4096,1)];
            float2 Pc = b1[SKM(r,1)], Pd = b1[SKM(r + 4096,1)];
            float2 Zq = cadd(Pa, Pb), Zq4 = csub(Pa, Pb);
            float2 Zr = cadd(Pc, Pd), Znq = csub(Pc, Pd);
            float2 Eq = twh[q];
            float2 Er = make_float2(-Eq.y, -Eq.x);        // E(4096-q)
            float2 Xq, Xnq, Xr, Xpq;
            unpack_pair(Zq, Znq, Eq, &Xq, &Xnq);
            unpack_pair(Zr, Zq4, Er, &Xr, &Xpq);
            Kc[q]         = make_float2(Xq.x * inv,  Xq.y * inv);
            Kc[N_FFT - q] = make_float2(Xnq.x * inv, Xnq.y * inv);
            Kc[r]         = make_float2(Xr.x * inv,  Xr.y * inv);
            Kc[4096 + q]  = make_float2(Xpq.x * inv, Xpq.y * inv);
        }
    }
}

// ---------------------------------------------------------------------------
__global__ void __launch_bounds__(NT, 1) conv_kernel(const float* __restrict__ x,
                                                     float* __restrict__ out) {
    extern __shared__ float2 sm2[];
    float2* b0  = sm2;
    float2* b1  = sm2 + BUF_PAD;
    float2* tws = sm2 + 2 * BUF_PAD;
    float2* twh = tws + 7 * TWT;

    const int row = blockIdx.x;
    const int c   = row & (NCHAN - 1);
    const int tid = threadIdx.x;
    const float2* xr = (const float2*)(x + (size_t)row * L_SEQ);

    fill_tw(tws, twh, tid);
    __syncthreads();

    {   // fwd stage 1: global read fused (upper half zero) -> b0 (skew 1)
        float2 v[8];
#pragma unroll
        for (int j = 0; j < 4; j++) v[j] = xr[tid + (j << 10)];
        dft8_half(v);
        stage1_write(b0, v, tws, tid);
    }
    __syncthreads();
    stage_r8<0,1,2>(b0, b1, tws, 8, tid);   __syncthreads();
    stage_r8<0,2,1>(b1, b0, tws, 64, tid);  __syncthreads();
    stage_r8<0,1,1>(b0, b1, tws, 512, tid); __syncthreads();
    // P = b1 (skew 1)

    // fused: fwd r2 finisher + spectral multiply + inv r2 opener -> b0 (skew 1)
    const float2* Kc = g_kspec + (size_t)c * (N_FFT + 1);
#pragma unroll 1
    for (int u = 0; u < 2; u++) {
        const int q = tid + (u << 10);
        if (q == 0) {
            float2 Pa = b1[SKM(0,1)],    Pb = b1[SKM(4096,1)];
            float2 Pc = b1[SKM(2048,1)], Pd = b1[SKM(6144,1)];
            float2 Z0 = cadd(Pa, Pb), Z4 = csub(Pa, Pb);
            float2 Z2 = cadd(Pc, Pd), Z6 = csub(Pc, Pd);
            float X0 = Z0.x + Z0.y, XN = Z0.x - Z0.y;
            float2 K0 = Kc[0], KN = Kc[N_FFT];
            float2 Y0 = make_float2(X0 * K0.x, X0 * K0.y);
            float2 YN = make_float2(XN * KN.x, XN * KN.y);
            float2 Ay = make_float2(0.5f * (Y0.x + YN.x), 0.5f * (Y0.y - YN.y));
            float2 Dy = make_float2(0.5f * (Y0.x - YN.x), 0.5f * (Y0.y + YN.y));
            float2 W0 = make_float2(Ay.x - Dy.y, Ay.y + Dy.x);
            float2 W4, Wd;
            spec_pair(Z4, Z4, Kc[4096], Kc[4096], make_float2(0.f, -1.f), &W4, &Wd);
            float2 W2, W6;
            spec_pair(Z2, Z6, Kc[2048], Kc[6144], twh[2048], &W2, &W6);
            b0[SKM(0,1)] = cadd(W0, W4);
            b0[SKM(1,1)] = csub(W0, W4);
            b0[SKM(4096,1)] = cadd(W2, W6);
            float2 t = csub(W2, W6);                 // * winv(2048) = i
            b0[SKM(4097,1)] = make_float2(-t.y, t.x);
        } else {
            const int r = 4096 - q;
            float2 Pa = b1[SKM(q,1)], Pb = b1[SKM(q + 4096,1)];
            float2 Pc = b1[SKM(r,1)], Pd = b1[SKM(r + 4096,1)];
            float2 Zq = cadd(Pa, Pb), Zq4 = csub(Pa, Pb);
            float2 Zr = cadd(Pc, Pd), Znq = csub(Pc, Pd);
            float2 Eq = twh[q];
            float2 Er = make_float2(-Eq.y, -Eq.x);
            float2 Wq, Wnq, Wr, Wpq;
            spec_pair(Zq, Znq, Kc[q], Kc[N_FFT - q], Eq, &Wq, &Wnq);
            spec_pair(Zr, Zq4, Kc[r], Kc[4096 + q], Er, &Wr, &Wpq);
            float2 wq = cmul(Eq, Eq);                 // W^q
            float2 wr = make_float2(-wq.x, wq.y);     // Er^2 = -conj(Eq^2)
            b0[SKM(2 * q, 1)]     = cadd(Wq, Wpq);
            b0[SKM(2 * q + 1, 1)] = cmulc(csub(Wq, Wpq), wq);
            b0[SKM(2 * r, 1)]     = cadd(Wr, Wnq);
            b0[SKM(2 * r + 1, 1)] = cmulc(csub(Wr, Wnq), wr);
        }
    }
    __syncthreads();

    stage_r8<1,1,2>(b0, b1, tws, 2, tid);   __syncthreads();  // s=2 W conflict-free under SK2
    stage_r8<1,2,1>(b1, b0, tws, 16, tid);  __syncthreads();
    stage_r8<1,1,1>(b0, b1, tws, 128, tid); __syncthreads();

    {   // final inverse stage s=1024 (twiddle-free): store first half to global
        float2 v[8];
#pragma unroll
        for (int j = 0; j < 8; j++) v[j] = b1[SKM(tid + (j << 10), 1)];
        dft8<1>(v);
        float2* outr = (float2*)(out + (size_t)row * L_SEQ);
#pragma unroll
        for (int j = 0; j < 4; j++) outr[tid + (j << 10)] = v[j];
    }
}

// ---------------------------------------------------------------------------
extern "C" void kernel_launch(void* const* d_in, const int* in_sizes, int n_in,
                              void* d_out, int out_size) {
    const float* x;
    const float* kern;
    if (in_sizes[0] == NROWS * L_SEQ) {
        x    = (const float*)d_in[0];
        kern = (const float*)d_in[1];
    } else {
        x    = (const float*)d_in[1];
        kern = (const float*)d_in[0];
    }
    float* out = (float*)d_out;

    cudaFuncSetAttribute(kspec_kernel, cudaFuncAttributeMaxDynamicSharedMemorySize, SMEM_BYTES);
    cudaFuncSetAttribute(conv_kernel,  cudaFuncAttributeMaxDynamicSharedMemorySize, SMEM_BYTES);

    kspec_kernel<<<NCHAN, NT, SMEM_BYTES>>>(kern);
    conv_kernel<<<NROWS, NT, SMEM_BYTES>>>(x, out);
}